// round 10
// baseline (speedup 1.0000x reference)
#include <cuda_runtime.h>
#include <cstdint>

// UpsampleLayer2D quadrant depth-to-space:
// out[b, r2, c2, co] = x[b, r2%R, c2%C, 4*co + k],  k = 2*(r2>=R) + (c2>=C)
// B=32, R=C=200, Cin=64, Co=16.
//
// R10: identical to the R2 optimum (one item/thread, 4x LDG.128 .cs,
// register transpose, 4x STG.128, block 512, exact grid) EXCEPT stores use
// write-through (__stwt) instead of streaming (__stcs). Completes the store
// policy matrix {wb: -25%, cs: best, wt: ?}. Rationale: .wt keeps store
// lines out of L2 residency entirely, freeing LTS slots for the read stream.

static constexpr int B  = 32;
static constexpr int R  = 200;
static constexpr int C  = 200;
static constexpr int CO = 16;            // output channels
static constexpr unsigned PIX = B * R * C;          // 1,280,000 pixels
static constexpr unsigned NTHREADS = PIX * 4;       // 5,120,000 (co groups of 4)

// float4 strides in the output [B, 2R, 2C, CO]:
static constexpr size_t OUT_ROW_F4  = (size_t)(2 * C) * CO / 4;   // 1600
static constexpr size_t Q_COL_OFF   = (size_t)C * CO / 4;         // 800
static constexpr size_t Q_ROW_OFF   = (size_t)R * OUT_ROW_F4;     // 320000

__global__ __launch_bounds__(512) void upsample2d_kernel(
    const float4* __restrict__ x4, float4* __restrict__ out4)
{
    unsigned g = blockIdx.x * 512u + threadIdx.x;   // grid sized exactly
    unsigned co4 = g & 3u;          // which group of 4 output channels
    unsigned pix = g >> 2;          // input pixel index

    unsigned c  = pix % (unsigned)C;
    unsigned rb = pix / (unsigned)C;
    unsigned r  = rb % (unsigned)R;
    unsigned b  = rb / (unsigned)R;

    const float4* src = x4 + (size_t)pix * 16 + (size_t)co4 * 4;
    float4 v0 = __ldcs(src + 0);
    float4 v1 = __ldcs(src + 1);
    float4 v2 = __ldcs(src + 2);
    float4 v3 = __ldcs(src + 3);

    size_t opix = ((size_t)b * (2 * R) + r) * (2 * C) + c;  // quadrant-0 pixel
    size_t o0   = opix * 4 + co4;                            // float4 index

    __stwt(out4 + o0,                         make_float4(v0.x, v1.x, v2.x, v3.x)); // TL
    __stwt(out4 + o0 + Q_COL_OFF,             make_float4(v0.y, v1.y, v2.y, v3.y)); // TR
    __stwt(out4 + o0 + Q_ROW_OFF,             make_float4(v0.z, v1.z, v2.z, v3.z)); // BL
    __stwt(out4 + o0 + Q_ROW_OFF + Q_COL_OFF, make_float4(v0.w, v1.w, v2.w, v3.w)); // BR
}

extern "C" void kernel_launch(void* const* d_in, const int* in_sizes, int n_in,
                              void* d_out, int out_size)
{
    const float4* x4   = (const float4*)d_in[0];
    float4*       out4 = (float4*)d_out;

    // NTHREADS = 5,120,000 = 10000 * 512 exactly; no bounds check needed.
    upsample2d_kernel<<<NTHREADS / 512, 512>>>(x4, out4);
}

// round 11
// speedup vs baseline: 1.3379x; 1.3379x over previous
#include <cuda_runtime.h>
#include <cstdint>

// UpsampleLayer2D quadrant depth-to-space:
// out[b, r2, c2, co] = x[b, r2%R, c2%C, 4*co + k],  k = 2*(r2>=R) + (c2>=C)
// B=32, R=C=200, Cin=64, Co=16.
//
// FINAL — the measured optimum over the full knob matrix (R0-R10):
//  - one work item (pixel x 4-output-channel group) per thread
//  - 4 front-batched LDG.128: each warp reads 2KB fully contiguous
//  - 4x4 register transpose (no smem, no syncs)
//  - 4 STG.128, one per quadrant: warp writes 512B contiguous per quadrant,
//    full 128B-line coverage -> no read-for-ownership
//  - streaming policy on BOTH sides (__ldcs/__stcs). Store policy matrix:
//    {wb: 131.6us, wt: 131.5us, cs: 98.2us} — .cs drain path is worth 25%.
//  - block 512 (beats 256/1024), one-shot exact grid (beats persistent by
//    11%), MLP=4 (MLP=8 trades occupancy 1:1), 30 regs.
// Measured: 98.2us, 7.2 TB/s combined R+W ~= 90% of 8TB/s spec — the mixed
// read/write HBM turnaround ceiling for this touch-once 655MB shuffle.

static constexpr int B  = 32;
static constexpr int R  = 200;
static constexpr int C  = 200;
static constexpr int CO = 16;            // output channels
static constexpr unsigned PIX = B * R * C;          // 1,280,000 pixels
static constexpr unsigned NTHREADS = PIX * 4;       // 5,120,000 (co groups of 4)

// float4 strides in the output [B, 2R, 2C, CO]:
static constexpr size_t OUT_ROW_F4  = (size_t)(2 * C) * CO / 4;   // 1600
static constexpr size_t Q_COL_OFF   = (size_t)C * CO / 4;         // 800
static constexpr size_t Q_ROW_OFF   = (size_t)R * OUT_ROW_F4;     // 320000

__global__ __launch_bounds__(512) void upsample2d_kernel(
    const float4* __restrict__ x4, float4* __restrict__ out4)
{
    unsigned g = blockIdx.x * 512u + threadIdx.x;   // grid sized exactly
    unsigned co4 = g & 3u;          // which group of 4 output channels
    unsigned pix = g >> 2;          // input pixel index

    unsigned c  = pix % (unsigned)C;
    unsigned rb = pix / (unsigned)C;
    unsigned r  = rb % (unsigned)R;
    unsigned b  = rb / (unsigned)R;

    const float4* src = x4 + (size_t)pix * 16 + (size_t)co4 * 4;
    float4 v0 = __ldcs(src + 0);
    float4 v1 = __ldcs(src + 1);
    float4 v2 = __ldcs(src + 2);
    float4 v3 = __ldcs(src + 3);

    size_t opix = ((size_t)b * (2 * R) + r) * (2 * C) + c;  // quadrant-0 pixel
    size_t o0   = opix * 4 + co4;                            // float4 index

    __stcs(out4 + o0,                         make_float4(v0.x, v1.x, v2.x, v3.x)); // TL
    __stcs(out4 + o0 + Q_COL_OFF,             make_float4(v0.y, v1.y, v2.y, v3.y)); // TR
    __stcs(out4 + o0 + Q_ROW_OFF,             make_float4(v0.z, v1.z, v2.z, v3.z)); // BL
    __stcs(out4 + o0 + Q_ROW_OFF + Q_COL_OFF, make_float4(v0.w, v1.w, v2.w, v3.w)); // BR
}

extern "C" void kernel_launch(void* const* d_in, const int* in_sizes, int n_in,
                              void* d_out, int out_size)
{
    const float4* x4   = (const float4*)d_in[0];
    float4*       out4 = (float4*)d_out;

    // NTHREADS = 5,120,000 = 10000 * 512 exactly; no bounds check needed.
    upsample2d_kernel<<<NTHREADS / 512, 512>>>(x4, out4);
}

// round 12
// speedup vs baseline: 1.3383x; 1.0003x over previous
#include <cuda_runtime.h>
#include <cstdint>

// UpsampleLayer2D quadrant depth-to-space:
// out[b, r2, c2, co] = x[b, r2%R, c2%C, 4*co + k],  k = 2*(r2>=R) + (c2>=C)
// B=32, R=C=200, Cin=64, Co=16.
//
// FINAL — measured optimum over the complete knob matrix (R0-R11):
//  - one work item (pixel x 4-output-channel group) per thread
//  - 4 front-batched LDG.128: each warp reads 2KB fully contiguous
//  - 4x4 register transpose (no smem, no syncs)
//  - 4 STG.128, one per quadrant: warp writes 512B contiguous per quadrant,
//    full 128B-line coverage -> no read-for-ownership
//  - streaming policy BOTH sides (__ldcs/__stcs). Store policy measured:
//    {wb: 131.6us, wt: 131.5us, cs: 98.2us} — the .cs drain path is worth 25%.
//  - block 512 (beats 256/1024), one-shot exact grid (beats persistent +11%),
//    MLP=4 (MLP=8 trades occupancy 1:1), 30 regs, ~70% achieved occupancy.
// Measured: 98.2us total / 92.2us kernel, 7.2 TB/s combined R+W = 90% of
// 8TB/s spec — the mixed read/write HBM turnaround ceiling for this
// touch-once 655MB shuffle. LDG.256 proved flat (DRAM-bound, not issue).

static constexpr int B  = 32;
static constexpr int R  = 200;
static constexpr int C  = 200;
static constexpr int CO = 16;            // output channels
static constexpr unsigned PIX = B * R * C;          // 1,280,000 pixels
static constexpr unsigned NTHREADS = PIX * 4;       // 5,120,000 (co groups of 4)

// float4 strides in the output [B, 2R, 2C, CO]:
static constexpr size_t OUT_ROW_F4  = (size_t)(2 * C) * CO / 4;   // 1600
static constexpr size_t Q_COL_OFF   = (size_t)C * CO / 4;         // 800
static constexpr size_t Q_ROW_OFF   = (size_t)R * OUT_ROW_F4;     // 320000

__global__ __launch_bounds__(512) void upsample2d_kernel(
    const float4* __restrict__ x4, float4* __restrict__ out4)
{
    unsigned g = blockIdx.x * 512u + threadIdx.x;   // grid sized exactly
    unsigned co4 = g & 3u;          // which group of 4 output channels
    unsigned pix = g >> 2;          // input pixel index

    unsigned c  = pix % (unsigned)C;
    unsigned rb = pix / (unsigned)C;
    unsigned r  = rb % (unsigned)R;
    unsigned b  = rb / (unsigned)R;

    const float4* src = x4 + (size_t)pix * 16 + (size_t)co4 * 4;
    float4 v0 = __ldcs(src + 0);
    float4 v1 = __ldcs(src + 1);
    float4 v2 = __ldcs(src + 2);
    float4 v3 = __ldcs(src + 3);

    size_t opix = ((size_t)b * (2 * R) + r) * (2 * C) + c;  // quadrant-0 pixel
    size_t o0   = opix * 4 + co4;                            // float4 index

    __stcs(out4 + o0,                         make_float4(v0.x, v1.x, v2.x, v3.x)); // TL
    __stcs(out4 + o0 + Q_COL_OFF,             make_float4(v0.y, v1.y, v2.y, v3.y)); // TR
    __stcs(out4 + o0 + Q_ROW_OFF,             make_float4(v0.z, v1.z, v2.z, v3.z)); // BL
    __stcs(out4 + o0 + Q_ROW_OFF + Q_COL_OFF, make_float4(v0.w, v1.w, v2.w, v3.w)); // BR
}

extern "C" void kernel_launch(void* const* d_in, const int* in_sizes, int n_in,
                              void* d_out, int out_size)
{
    const float4* x4   = (const float4*)d_in[0];
    float4*       out4 = (float4*)d_out;

    // NTHREADS = 5,120,000 = 10000 * 512 exactly; no bounds check needed.
    upsample2d_kernel<<<NTHREADS / 512, 512>>>(x4, out4);
}

// round 15
// speedup vs baseline: 1.3414x; 1.0023x over previous
#include <cuda_runtime.h>
#include <cstdint>

// UpsampleLayer2D quadrant depth-to-space:
// out[b, r2, c2, co] = x[b, r2%R, c2%C, 4*co + k],  k = 2*(r2>=R) + (c2>=C)
// B=32, R=C=200, Cin=64, Co=16.
//
// FINAL — measured optimum over the complete knob matrix (R0-R12), stable
// across 4 reproductions (98.24/98.34/98.30/98.27 us):
//  - one work item (pixel x 4-output-channel group) per thread
//  - 4 front-batched LDG.128: each warp reads 2KB fully contiguous
//  - 4x4 register transpose (no smem, no syncs)
//  - 4 STG.128, one per quadrant: warp writes 512B contiguous per quadrant,
//    full 128B-line coverage -> no read-for-ownership
//  - streaming policy BOTH sides (__ldcs/__stcs). Store policy measured:
//    {wb: 131.6us, wt: 131.5us, cs: 98.2us} — the .cs drain path is worth 25%.
//  - block 512 (beats 256/1024), one-shot exact grid (beats persistent +11%),
//    MLP=4 (MLP=8 trades occupancy 1:1), 30 regs.
// 7.2 TB/s combined R+W = ~90% of 8TB/s spec — the mixed read/write HBM
// turnaround ceiling for this touch-once 655MB shuffle. LDG.256 flat
// (DRAM-bound, not issue-bound); TMA path-equivalent per B300 LTS cap.

static constexpr int B  = 32;
static constexpr int R  = 200;
static constexpr int C  = 200;
static constexpr int CO = 16;            // output channels
static constexpr unsigned PIX = B * R * C;          // 1,280,000 pixels
static constexpr unsigned NTHREADS = PIX * 4;       // 5,120,000 (co groups of 4)

// float4 strides in the output [B, 2R, 2C, CO]:
static constexpr size_t OUT_ROW_F4  = (size_t)(2 * C) * CO / 4;   // 1600
static constexpr size_t Q_COL_OFF   = (size_t)C * CO / 4;         // 800
static constexpr size_t Q_ROW_OFF   = (size_t)R * OUT_ROW_F4;     // 320000

__global__ __launch_bounds__(512) void upsample2d_kernel(
    const float4* __restrict__ x4, float4* __restrict__ out4)
{
    unsigned g = blockIdx.x * 512u + threadIdx.x;   // grid sized exactly
    unsigned co4 = g & 3u;          // which group of 4 output channels
    unsigned pix = g >> 2;          // input pixel index

    unsigned c  = pix % (unsigned)C;
    unsigned rb = pix / (unsigned)C;
    unsigned r  = rb % (unsigned)R;
    unsigned b  = rb / (unsigned)R;

    const float4* src = x4 + (size_t)pix * 16 + (size_t)co4 * 4;
    float4 v0 = __ldcs(src + 0);
    float4 v1 = __ldcs(src + 1);
    float4 v2 = __ldcs(src + 2);
    float4 v3 = __ldcs(src + 3);

    size_t opix = ((size_t)b * (2 * R) + r) * (2 * C) + c;  // quadrant-0 pixel
    size_t o0   = opix * 4 + co4;                            // float4 index

    __stcs(out4 + o0,                         make_float4(v0.x, v1.x, v2.x, v3.x)); // TL
    __stcs(out4 + o0 + Q_COL_OFF,             make_float4(v0.y, v1.y, v2.y, v3.y)); // TR
    __stcs(out4 + o0 + Q_ROW_OFF,             make_float4(v0.z, v1.z, v2.z, v3.z)); // BL
    __stcs(out4 + o0 + Q_ROW_OFF + Q_COL_OFF, make_float4(v0.w, v1.w, v2.w, v3.w)); // BR
}

extern "C" void kernel_launch(void* const* d_in, const int* in_sizes, int n_in,
                              void* d_out, int out_size)
{
    const float4* x4   = (const float4*)d_in[0];
    float4*       out4 = (float4*)d_out;

    // NTHREADS = 5,120,000 = 10000 * 512 exactly; no bounds check needed.
    upsample2d_kernel<<<NTHREADS / 512, 512>>>(x4, out4);
}